// round 9
// baseline (speedup 1.0000x reference)
#include <cuda_runtime.h>
#include <math.h>

// ---------------- problem constants ----------------
#define N_DIM 121
#define K_RAW 242            // stacked K = 2*N
#define NPAD  128
#define BM    128            // rows per block
#define BK    32             // k-chunk
#define BKP   36             // padded smem row stride (floats); conflict-free
#define NCHUNK 8             // 8*32 = 256 >= 242
#define B_MAX 32768

// g scratch (sigmoid outputs), real/imag planes. __device__ global = allowed scratch.
__device__ float g_scratch[2][B_MAX * N_DIM];

__device__ __forceinline__ float safe_ld(const float* p, long long idx, long long sz) {
    return (p != nullptr && idx >= 0 && idx < sz) ? p[idx] : 0.f;
}

// ---------------- GEMM + sigmoid kernel ----------------
// g[b,n] = sigmoid( sum_k z[b,k]*W[n,k] + sum_k v[b,k]*U[n,k] + bW[n] + bU[n] )
// blockIdx.y: 0 = real plane, 1 = imag plane. Static smem only (~37 KB).
extern "C" __global__ void __launch_bounds__(256)
gate_gemm_kernel(const float* __restrict__ z_r, const float* __restrict__ v_r,
                 const float* __restrict__ Wr,  const float* __restrict__ Wrb,
                 const float* __restrict__ Ur,  const float* __restrict__ Urb,
                 const float* __restrict__ z_i, const float* __restrict__ v_i,
                 const float* __restrict__ Wi,  const float* __restrict__ Wib,
                 const float* __restrict__ Ui,  const float* __restrict__ Uib,
                 long long sz_zv, long long sz_w, long long sz_b, int Brows)
{
    __shared__ float Ws[NPAD * BKP];   // weights chunk [n][k]
    __shared__ float As[BM * BKP];     // activation chunk [r][k]
    __shared__ float Bs[NPAD];         // combined bias

    const int part = blockIdx.y;
    const float* Z  = part ? z_i : z_r;
    const float* V  = part ? v_i : v_r;
    const float* W  = part ? Wi  : Wr;
    const float* U  = part ? Ui  : Ur;
    const float* Wb = part ? Wib : Wrb;
    const float* Ub = part ? Uib : Urb;

    const int tid  = threadIdx.x;
    const int lane = tid & 31;
    const int warp = tid >> 5;
    const int row0 = blockIdx.x * BM;

    if (tid < NPAD)
        Bs[tid] = (tid < N_DIM)
                    ? (safe_ld(Wb, tid, sz_b) + safe_ld(Ub, tid, sz_b)) : 0.f;

    // thread tile: 8 rows x 8 cols
    const int cn0 = lane & 15;                        // n = cn0 + 16*c
    const int rt0 = warp * 16 + ((lane >> 4) << 3);   // rows rt0..rt0+7

    float acc[8][8];
#pragma unroll
    for (int r = 0; r < 8; ++r)
#pragma unroll
        for (int c = 0; c < 8; ++c) acc[r][c] = 0.f;

    const float4* Ws4 = reinterpret_cast<const float4*>(Ws);
    const float4* As4 = reinterpret_cast<const float4*>(As);

    for (int kt = 0; kt < NCHUNK; ++kt) {
        __syncthreads();   // previous compute done before overwriting tiles

        // cooperative chunk load: idx -> (n, kl); consecutive tid = consecutive kl
        const int gk0 = kt * BK;
        for (int idx = tid; idx < NPAD * BK; idx += 256) {
            int n  = idx >> 5;
            int kl = idx & 31;
            int gk = gk0 + kl;

            // weights
            float wv = 0.f;
            if (n < N_DIM) {
                if (gk < N_DIM)      wv = safe_ld(W, (long long)n * N_DIM + gk, sz_w);
                else if (gk < K_RAW) wv = safe_ld(U, (long long)n * N_DIM + (gk - N_DIM), sz_w);
            }
            Ws[n * BKP + kl] = wv;

            // activations (row = n here, same index pattern)
            long long row = row0 + n;
            float av = 0.f;
            if (row < Brows) {
                if (gk < N_DIM)      av = safe_ld(Z, row * N_DIM + gk, sz_zv);
                else if (gk < K_RAW) av = safe_ld(V, row * N_DIM + (gk - N_DIM), sz_zv);
            }
            As[n * BKP + kl] = av;
        }
        __syncthreads();

        // compute: 8 float4 k-steps per chunk (row stride = BKP/4 = 9 float4)
#pragma unroll
        for (int j = 0; j < 8; ++j) {
            float4 w4[8];
#pragma unroll
            for (int c = 0; c < 8; ++c)
                w4[c] = Ws4[(cn0 + 16 * c) * 9 + j];
#pragma unroll
            for (int r = 0; r < 8; ++r) {
                float4 a4 = As4[(rt0 + r) * 9 + j];
#pragma unroll
                for (int c = 0; c < 8; ++c) {
                    acc[r][c] += a4.x * w4[c].x;
                    acc[r][c] += a4.y * w4[c].y;
                    acc[r][c] += a4.z * w4[c].z;
                    acc[r][c] += a4.w * w4[c].w;
                }
            }
        }
    }

    // epilogue: bias + sigmoid -> g_scratch
    float* gdst = g_scratch[part];
#pragma unroll
    for (int r = 0; r < 8; ++r) {
        long long row = row0 + rt0 + r;
        if (row >= Brows) continue;
#pragma unroll
        for (int c = 0; c < 8; ++c) {
            int n = cn0 + 16 * c;
            if (n < N_DIM) {
                float t = acc[r][c] + Bs[n];
                gdst[row * N_DIM + n] = 1.f / (1.f + __expf(-t));
            }
        }
    }
}

// ---------------- fused complex epilogue kernel ----------------
// x = (A_H_y + eta*(z-v)) / (w + eta);  u = x + v
// zo = g*u + (1-g)*z;  vo = v + x - zo
// Output layout: SIX BN-float planes, all reals first then all imags:
//   [x_re][z_re][v_re][x_im][z_im][v_im]
extern "C" __global__ void __launch_bounds__(256)
fuse_kernel(const float* __restrict__ ayr, const float* __restrict__ ayi,
            const float* __restrict__ zr,  const float* __restrict__ zi,
            const float* __restrict__ vr,  const float* __restrict__ vi,
            const float* __restrict__ wdr, const float* __restrict__ wdi,
            const float* __restrict__ raw_eta,
            float* __restrict__ out, int BN,
            long long sz_ay, long long sz_zv, long long sz_wd, long long sz_eta,
            long long out_floats)
{
    int idx = blockIdx.x * blockDim.x + threadIdx.x;
    if (idx >= BN) return;

    float re  = safe_ld(raw_eta, 0, sz_eta);
    float eta = fmaxf(re, 0.f) + log1pf(__expf(-fabsf(re)));

    int n = idx % N_DIM;

    float zpr = safe_ld(zr, idx, sz_zv), zpi = safe_ld(zi, idx, sz_zv);
    float vpr = safe_ld(vr, idx, sz_zv), vpi = safe_ld(vi, idx, sz_zv);

    float nr = safe_ld(ayr, idx, sz_ay) + eta * (zpr - vpr);
    float ni = safe_ld(ayi, idx, sz_ay) + eta * (zpi - vpi);
    float dr = safe_ld(wdr, n, sz_wd) + eta;
    float di = safe_ld(wdi, n, sz_wd);
    float inv = 1.f / (dr * dr + di * di);
    float xr = (nr * dr + ni * di) * inv;
    float xi = (ni * dr - nr * di) * inv;

    float ur = xr + vpr;
    float ui = xi + vpi;

    float gr = g_scratch[0][idx];
    float gi = g_scratch[1][idx];

    float zor = gr * ur - gi * ui + (1.f - gr) * zpr + gi * zpi;
    float zoi = gr * ui + gi * ur + (1.f - gr) * zpi - gi * zpr;

    float vor = vpr + xr - zor;
    float voi = vpi + xi - zoi;

    // plane order: x_re, z_re, v_re, x_im, z_im, v_im
    float res[6] = {xr, zor, vor, xi, zoi, voi};
#pragma unroll
    for (int p = 0; p < 6; ++p) {
        long long fi = (long long)p * BN + idx;
        if (fi < out_floats) out[fi] = res[p];
    }
}

// ---------------- launch ----------------
extern "C" void kernel_launch(void* const* d_in, const int* in_sizes, int n_in,
                              void* d_out, int out_size)
{
    const float* P[17];
    long long    S[17];
    for (int i = 0; i < 17; ++i) {
        P[i] = (i < n_in) ? (const float*)d_in[i] : nullptr;
        S[i] = (i < n_in) ? (long long)in_sizes[i] : 0;
    }
    const float *ayr = P[0],  *ayi = P[1];
    const float *zr  = P[2],  *zi  = P[3];
    const float *vr  = P[4],  *vi  = P[5];
    const float *wdr = P[6],  *wdi = P[7];
    const float *reta= P[8];
    const float *Wrw = P[9],  *Wrb = P[10];
    const float *Urw = P[11], *Urb = P[12];
    const float *Wiw = P[13], *Wib = P[14];
    const float *Uiw = P[15], *Uib = P[16];

    long long BNl = S[0];
    if (BNl > (long long)B_MAX * N_DIM) BNl = (long long)B_MAX * N_DIM;
    int BN = (int)BNl;
    int B  = BN / N_DIM;
    if (B < 1) B = 1;

    dim3 ggrid((B + BM - 1) / BM, 2);
    gate_gemm_kernel<<<ggrid, 256>>>(
        zr, vr, Wrw, Wrb, Urw, Urb,
        zi, vi, Wiw, Wib, Uiw, Uib,
        S[2], S[9], S[10], B);

    int fblocks = (BN + 255) / 256;
    fuse_kernel<<<fblocks, 256>>>(ayr, ayi, zr, zi, vr, vi, wdr, wdi, reta,
                                  (float*)d_out, BN,
                                  S[0], S[2], S[6], S[8],
                                  (long long)out_size);
}